// round 4
// baseline (speedup 1.0000x reference)
#include <cuda_runtime.h>
#include <math.h>

#define N_NODES 100000
#define N_EDGES 200000
#define H 128
#define H2 256
#define H3 384
#define NBUCK 21          // 7 levels x 3 gate types
#define MSG_TE 16
#define GRU_TN 8

// ---------------- device scratch (static: no allocations allowed) ----------
__device__ float g_msg[N_NODES * H];           // scatter-add target, zeroed each launch
__device__ float g_hs_type[6 * H];             // per-gate-type hs row
__device__ float g_wihT[3 * H * H3];           // transposed GRU weights
__device__ float g_whhT[3 * H * H3];
__device__ int g_ecount[NBUCK];
__device__ int g_eoff[NBUCK + 1];
__device__ int g_ecur[NBUCK];
__device__ int g_ncount[NBUCK];
__device__ int g_noff[NBUCK + 1];
__device__ int g_ncur[NBUCK];
__device__ int g_elist[N_EDGES];
__device__ int g_nlist[N_NODES];

__device__ __forceinline__ int gate_gi(int g) {
    // GATE_CODES = (3, 2, 5) -> gi 0, 1, 2
    return (g == 3) ? 0 : (g == 2) ? 1 : (g == 5) ? 2 : -1;
}

// ---------------- setup kernels -------------------------------------------

__global__ void k_init_counts() {
    int t = threadIdx.x;
    if (t < NBUCK) { g_ecount[t] = 0; g_ncount[t] = 0; }
}

// hs_type[g][j] = concat(Ws[g], Wt[g]) @ hs_W + hs_b
__global__ void k_hs_type(const float* __restrict__ Ws, const float* __restrict__ Wt,
                          const float* __restrict__ hsW, const float* __restrict__ hsb) {
    int g = blockIdx.x;      // 0..5
    int j = threadIdx.x;     // 0..127
    float acc = hsb[j];
#pragma unroll 4
    for (int k = 0; k < H; k++)
        acc = fmaf(Ws[g * H + k], hsW[k * H + j], acc);
#pragma unroll 4
    for (int k = 0; k < H; k++)
        acc = fmaf(Wt[g * H + k], hsW[(H + k) * H + j], acc);
    g_hs_type[g * H + j] = acc;
}

// transpose GRU weights: wihT[gi][k][r] = wih[gi][r][k]
__global__ void k_transpose(const float* __restrict__ wih, const float* __restrict__ whh) {
    const int total = 3 * H3 * H;
    for (int i = blockIdx.x * blockDim.x + threadIdx.x; i < total; i += gridDim.x * blockDim.x) {
        int gi = i / (H3 * H);
        int rem = i - gi * (H3 * H);
        int r = rem / H;
        int k = rem - r * H;
        g_wihT[gi * H * H3 + k * H3 + r] = wih[i];
        g_whhT[gi * H * H3 + k * H3 + r] = whh[i];
    }
}

// write hs to out[0:NH), zero hf region out[NH:2NH), zero msg buffer
__global__ void k_hs_fill(float* __restrict__ out, const int* __restrict__ gate) {
    const int total = N_NODES * H;
    for (int i = blockIdx.x * blockDim.x + threadIdx.x; i < total; i += gridDim.x * blockDim.x) {
        int node = i >> 7;
        int j = i & (H - 1);
        out[i] = g_hs_type[gate[node] * H + j];
        out[total + i] = 0.0f;
        g_msg[i] = 0.0f;
    }
}

// count edges/nodes per (level, gate-type) bucket
__global__ void k_count(const int* __restrict__ ei, const int* __restrict__ gate,
                        const int* __restrict__ lvl) {
    const int total = N_EDGES + N_NODES;
    for (int i = blockIdx.x * blockDim.x + threadIdx.x; i < total; i += gridDim.x * blockDim.x) {
        if (i < N_EDGES) {
            int d = ei[N_EDGES + i];
            int gi = gate_gi(gate[d]);
            int l = lvl[d];
            if (gi >= 0 && l >= 1 && l <= 7) atomicAdd(&g_ecount[(l - 1) * 3 + gi], 1);
        } else {
            int n = i - N_EDGES;
            int gi = gate_gi(gate[n]);
            int l = lvl[n];
            if (gi >= 0 && l >= 1 && l <= 7) atomicAdd(&g_ncount[(l - 1) * 3 + gi], 1);
        }
    }
}

__global__ void k_scan() {
    if (threadIdx.x == 0) {
        int s = 0;
        for (int b = 0; b < NBUCK; b++) { g_eoff[b] = s; g_ecur[b] = s; s += g_ecount[b]; }
        g_eoff[NBUCK] = s;
        s = 0;
        for (int b = 0; b < NBUCK; b++) { g_noff[b] = s; g_ncur[b] = s; s += g_ncount[b]; }
        g_noff[NBUCK] = s;
    }
}

__global__ void k_fill_lists(const int* __restrict__ ei, const int* __restrict__ gate,
                             const int* __restrict__ lvl) {
    const int total = N_EDGES + N_NODES;
    for (int i = blockIdx.x * blockDim.x + threadIdx.x; i < total; i += gridDim.x * blockDim.x) {
        if (i < N_EDGES) {
            int d = ei[N_EDGES + i];
            int gi = gate_gi(gate[d]);
            int l = lvl[d];
            if (gi >= 0 && l >= 1 && l <= 7) {
                int pos = atomicAdd(&g_ecur[(l - 1) * 3 + gi], 1);
                g_elist[pos] = i;
            }
        } else {
            int n = i - N_EDGES;
            int gi = gate_gi(gate[n]);
            int l = lvl[n];
            if (gi >= 0 && l >= 1 && l <= 7) {
                int pos = atomicAdd(&g_ncur[(l - 1) * 3 + gi], 1);
                g_nlist[pos] = n;
            }
        }
    }
}

// ---------------- per-level message kernel --------------------------------
// Block = 128 threads, 16-edge tile. x = [hs[src], hf[src]] -> 3-layer MLP ->
// atomicAdd scatter to g_msg[dst].
__global__ void __launch_bounds__(H) k_msg(const int* __restrict__ ei,
                      const float* __restrict__ outbuf,
                      const float* __restrict__ w1, const float* __restrict__ b1,
                      const float* __restrict__ w2, const float* __restrict__ b2,
                      const float* __restrict__ w3, const float* __restrict__ b3,
                      int bucket) {
    __shared__ float xs[MSG_TE][H2];
    __shared__ float h1s[MSG_TE][H];
    __shared__ int sdst[MSG_TE];

    const int lo = g_eoff[bucket];
    const int hi = g_eoff[bucket + 1];
    const int j = threadIdx.x;
    const float* hf = outbuf + (size_t)N_NODES * H;

    for (int start = lo + blockIdx.x * MSG_TE; start < hi; start += gridDim.x * MSG_TE) {
        const int ne = min(MSG_TE, hi - start);
#pragma unroll
        for (int e = 0; e < MSG_TE; e++) {
            if (e < ne) {
                int eid = g_elist[start + e];
                int src = ei[eid];
                if (j == 0) sdst[e] = ei[N_EDGES + eid];
                xs[e][j] = outbuf[src * H + j];
                xs[e][H + j] = hf[src * H + j];
            } else {
                xs[e][j] = 0.0f;
                xs[e][H + j] = 0.0f;
            }
        }
        __syncthreads();

        float acc[MSG_TE];
#pragma unroll
        for (int e = 0; e < MSG_TE; e++) acc[e] = 0.0f;
#pragma unroll 2
        for (int k = 0; k < H2; k++) {
            float w = __ldg(&w1[k * H + j]);
#pragma unroll
            for (int e = 0; e < MSG_TE; e++) acc[e] = fmaf(xs[e][k], w, acc[e]);
        }
        float bb = __ldg(&b1[j]);
#pragma unroll
        for (int e = 0; e < MSG_TE; e++) h1s[e][j] = fmaxf(acc[e] + bb, 0.0f);
        __syncthreads();

#pragma unroll
        for (int e = 0; e < MSG_TE; e++) acc[e] = 0.0f;
#pragma unroll 2
        for (int k = 0; k < H; k++) {
            float w = __ldg(&w2[k * H + j]);
#pragma unroll
            for (int e = 0; e < MSG_TE; e++) acc[e] = fmaf(h1s[e][k], w, acc[e]);
        }
        bb = __ldg(&b2[j]);
#pragma unroll
        for (int e = 0; e < MSG_TE; e++) xs[e][j] = fmaxf(acc[e] + bb, 0.0f);  // h2 reuses xs
        __syncthreads();

#pragma unroll
        for (int e = 0; e < MSG_TE; e++) acc[e] = 0.0f;
#pragma unroll 2
        for (int k = 0; k < H; k++) {
            float w = __ldg(&w3[k * H + j]);
#pragma unroll
            for (int e = 0; e < MSG_TE; e++) acc[e] = fmaf(xs[e][k], w, acc[e]);
        }
        bb = __ldg(&b3[j]);
        for (int e = 0; e < ne; e++) {
            atomicAdd(&g_msg[sdst[e] * H + j], acc[e] + bb);
        }
        __syncthreads();
    }
}

// ---------------- per-level GRU kernel ------------------------------------
// Block = 128 threads, 8-node tile. Thread j owns feature j -> computes gin/gh
// rows j, j+H, j+2H so the whole gate math stays in registers.
__global__ void __launch_bounds__(H) k_gru(const float* __restrict__ bih, const float* __restrict__ bhh,
                      float* __restrict__ outbuf, int bucket, int gi) {
    __shared__ float ms[GRU_TN][H];
    __shared__ float ho[GRU_TN][H];
    __shared__ int snode[GRU_TN];

    const float* __restrict__ wihT = g_wihT + gi * H * H3;
    const float* __restrict__ whhT = g_whhT + gi * H * H3;
    const int lo = g_noff[bucket];
    const int hi = g_noff[bucket + 1];
    const int j = threadIdx.x;
    float* hf = outbuf + (size_t)N_NODES * H;

    for (int start = lo + blockIdx.x * GRU_TN; start < hi; start += gridDim.x * GRU_TN) {
        const int nn = min(GRU_TN, hi - start);
#pragma unroll
        for (int e = 0; e < GRU_TN; e++) {
            if (e < nn) {
                int node = g_nlist[start + e];
                if (j == 0) snode[e] = node;
                ms[e][j] = g_msg[node * H + j];
                ho[e][j] = hf[node * H + j];
            } else {
                ms[e][j] = 0.0f;
                ho[e][j] = 0.0f;
            }
        }
        __syncthreads();

        float air[GRU_TN], aiz[GRU_TN], ain[GRU_TN];
        float ahr[GRU_TN], ahz[GRU_TN], ahn[GRU_TN];
#pragma unroll
        for (int e = 0; e < GRU_TN; e++) {
            air[e] = 0.0f; aiz[e] = 0.0f; ain[e] = 0.0f;
            ahr[e] = 0.0f; ahz[e] = 0.0f; ahn[e] = 0.0f;
        }
        for (int k = 0; k < H; k++) {
            float wr = __ldg(&wihT[k * H3 + j]);
            float wz = __ldg(&wihT[k * H3 + H + j]);
            float wn = __ldg(&wihT[k * H3 + 2 * H + j]);
            float vr = __ldg(&whhT[k * H3 + j]);
            float vz = __ldg(&whhT[k * H3 + H + j]);
            float vn = __ldg(&whhT[k * H3 + 2 * H + j]);
#pragma unroll
            for (int e = 0; e < GRU_TN; e++) {
                float m = ms[e][k];
                float h = ho[e][k];
                air[e] = fmaf(m, wr, air[e]);
                aiz[e] = fmaf(m, wz, aiz[e]);
                ain[e] = fmaf(m, wn, ain[e]);
                ahr[e] = fmaf(h, vr, ahr[e]);
                ahz[e] = fmaf(h, vz, ahz[e]);
                ahn[e] = fmaf(h, vn, ahn[e]);
            }
        }
        float bir = __ldg(&bih[j]), biz = __ldg(&bih[H + j]), bin_ = __ldg(&bih[2 * H + j]);
        float bhr = __ldg(&bhh[j]), bhz = __ldg(&bhh[H + j]), bhn = __ldg(&bhh[2 * H + j]);
        for (int e = 0; e < nn; e++) {
            float r = 1.0f / (1.0f + expf(-(air[e] + bir + ahr[e] + bhr)));
            float z = 1.0f / (1.0f + expf(-(aiz[e] + biz + ahz[e] + bhz)));
            float nst = tanhf(ain[e] + bin_ + r * (ahn[e] + bhn));
            float hold = ho[e][j];
            hf[snode[e] * H + j] = (1.0f - z) * nst + z * hold;
        }
        __syncthreads();
    }
}

// ---------------- launch ---------------------------------------------------

extern "C" void kernel_launch(void* const* d_in, const int* in_sizes, int n_in,
                              void* d_out, int out_size) {
    const int* gate    = (const int*)d_in[0];
    const int* flevel  = (const int*)d_in[1];
    const int* ei      = (const int*)d_in[2];
    const float* Ws    = (const float*)d_in[3];
    const float* Wt    = (const float*)d_in[4];
    const float* hs_W  = (const float*)d_in[5];
    const float* hs_b  = (const float*)d_in[6];
    const float* w1    = (const float*)d_in[7];
    const float* b1    = (const float*)d_in[8];
    const float* w2    = (const float*)d_in[9];
    const float* b2    = (const float*)d_in[10];
    const float* w3    = (const float*)d_in[11];
    const float* b3    = (const float*)d_in[12];
    const float* wih   = (const float*)d_in[13];
    const float* whh   = (const float*)d_in[14];
    const float* bih   = (const float*)d_in[15];
    const float* bhh   = (const float*)d_in[16];
    float* out = (float*)d_out;

    k_init_counts<<<1, 64>>>();
    k_hs_type<<<6, H>>>(Ws, Wt, hs_W, hs_b);
    k_transpose<<<256, 256>>>(wih, whh);
    k_hs_fill<<<8192, 256>>>(out, gate);
    k_count<<<1024, 256>>>(ei, gate, flevel);
    k_scan<<<1, 32>>>();
    k_fill_lists<<<1024, 256>>>(ei, gate, flevel);

    for (int lvl = 1; lvl <= 7; lvl++) {
        // all message kernels of this level first (they read the pre-level hf
        // snapshot), then all GRU updates (disjoint node sets per gate type)
        for (int gi = 0; gi < 3; gi++) {
            int b = (lvl - 1) * 3 + gi;
            k_msg<<<768, H>>>(ei, out,
                              w1 + (size_t)gi * H2 * H, b1 + gi * H,
                              w2 + (size_t)gi * H * H,  b2 + gi * H,
                              w3 + (size_t)gi * H * H,  b3 + gi * H,
                              b);
        }
        for (int gi = 0; gi < 3; gi++) {
            int b = (lvl - 1) * 3 + gi;
            k_gru<<<512, H>>>(bih + gi * H3, bhh + gi * H3, out, b, gi);
        }
    }
}

// round 7
// speedup vs baseline: 2.7122x; 2.7122x over previous
#include <cuda_runtime.h>
#include <math.h>

#define N_NODES 100000
#define N_EDGES 200000
#define H 128
#define H2 256
#define H3 384
#define NBUCK 21          // 7 levels x 3 gate types
#define MSG_TE 32         // edges per msg tile
#define GRU_TN 16         // nodes per gru tile

// ---------------- device scratch (static: no allocations allowed) ----------
__device__ float g_msg[(size_t)N_NODES * H];   // scatter-add target
__device__ float g_hs_type[6 * H];             // per-gate-type hs row
__device__ float g_wihT[3 * H * H3];           // transposed GRU input weights [gi][k][row]
__device__ int g_ecount[NBUCK];
__device__ int g_eoff[NBUCK + 1];
__device__ int g_ecur[NBUCK];
__device__ int g_etile[NBUCK + 1];
__device__ int g_ncount[NBUCK];
__device__ int g_noff[NBUCK + 1];
__device__ int g_ncur[NBUCK];
__device__ int g_ntile[NBUCK + 1];
__device__ int g_elist[N_EDGES];
__device__ int g_nlist[N_NODES];

__device__ __forceinline__ int gate_gi(int g) {
    // GATE_CODES = (3, 2, 5) -> gi 0, 1, 2
    return (g == 3) ? 0 : (g == 2) ? 1 : (g == 5) ? 2 : -1;
}

// ---------------- setup kernels -------------------------------------------

__global__ void k_init_counts() {
    int t = threadIdx.x;
    if (t < NBUCK) { g_ecount[t] = 0; g_ncount[t] = 0; }
}

// hs_type[g][j] = concat(Ws[g], Wt[g]) @ hs_W + hs_b
__global__ void k_hs_type(const float* __restrict__ Ws, const float* __restrict__ Wt,
                          const float* __restrict__ hsW, const float* __restrict__ hsb) {
    int g = blockIdx.x;      // 0..5
    int j = threadIdx.x;     // 0..127
    float acc = hsb[j];
#pragma unroll 4
    for (int k = 0; k < H; k++)
        acc = fmaf(Ws[g * H + k], hsW[k * H + j], acc);
#pragma unroll 4
    for (int k = 0; k < H; k++)
        acc = fmaf(Wt[g * H + k], hsW[(H + k) * H + j], acc);
    g_hs_type[g * H + j] = acc;
}

// transpose GRU input weights: wihT[gi][k][r] = wih[gi][r][k]
__global__ void k_transpose(const float* __restrict__ wih) {
    const int total = 3 * H3 * H;
    for (int i = blockIdx.x * blockDim.x + threadIdx.x; i < total; i += gridDim.x * blockDim.x) {
        int gi = i / (H3 * H);
        int rem = i - gi * (H3 * H);
        int r = rem / H;
        int k = rem - r * H;
        g_wihT[gi * H * H3 + k * H3 + r] = wih[i];
    }
}

// write hs to out[0:NH), zero hf region out[NH:2NH), zero msg buffer (float4)
__global__ void k_hs_fill(float4* __restrict__ out4, const int* __restrict__ gate) {
    const int total4 = N_NODES * (H / 4);
    const float4* hs4 = (const float4*)g_hs_type;
    float4* msg4 = (float4*)g_msg;
    const float4 z4 = make_float4(0.f, 0.f, 0.f, 0.f);
    for (int i = blockIdx.x * blockDim.x + threadIdx.x; i < total4; i += gridDim.x * blockDim.x) {
        int node = i >> 5;               // H/4 = 32 float4 per row
        int c = i & 31;
        out4[i] = hs4[gate[node] * 32 + c];
        out4[total4 + i] = z4;
        msg4[i] = z4;
    }
}

// count edges/nodes per (level, gate-type) bucket
__global__ void k_count(const int* __restrict__ ei, const int* __restrict__ gate,
                        const int* __restrict__ lvl) {
    const int total = N_EDGES + N_NODES;
    for (int i = blockIdx.x * blockDim.x + threadIdx.x; i < total; i += gridDim.x * blockDim.x) {
        if (i < N_EDGES) {
            int d = ei[N_EDGES + i];
            int gi = gate_gi(gate[d]);
            int l = lvl[d];
            if (gi >= 0 && l >= 1 && l <= 7) atomicAdd(&g_ecount[(l - 1) * 3 + gi], 1);
        } else {
            int n = i - N_EDGES;
            int gi = gate_gi(gate[n]);
            int l = lvl[n];
            if (gi >= 0 && l >= 1 && l <= 7) atomicAdd(&g_ncount[(l - 1) * 3 + gi], 1);
        }
    }
}

__global__ void k_scan() {
    if (threadIdx.x == 0) {
        int s = 0, st = 0;
        for (int b = 0; b < NBUCK; b++) {
            g_eoff[b] = s; g_ecur[b] = s; g_etile[b] = st;
            st += (g_ecount[b] + MSG_TE - 1) / MSG_TE;
            s += g_ecount[b];
        }
        g_eoff[NBUCK] = s; g_etile[NBUCK] = st;
        s = 0; st = 0;
        for (int b = 0; b < NBUCK; b++) {
            g_noff[b] = s; g_ncur[b] = s; g_ntile[b] = st;
            st += (g_ncount[b] + GRU_TN - 1) / GRU_TN;
            s += g_ncount[b];
        }
        g_noff[NBUCK] = s; g_ntile[NBUCK] = st;
    }
}

__global__ void k_fill_lists(const int* __restrict__ ei, const int* __restrict__ gate,
                             const int* __restrict__ lvl) {
    const int total = N_EDGES + N_NODES;
    for (int i = blockIdx.x * blockDim.x + threadIdx.x; i < total; i += gridDim.x * blockDim.x) {
        if (i < N_EDGES) {
            int d = ei[N_EDGES + i];
            int gi = gate_gi(gate[d]);
            int l = lvl[d];
            if (gi >= 0 && l >= 1 && l <= 7) {
                int pos = atomicAdd(&g_ecur[(l - 1) * 3 + gi], 1);
                g_elist[pos] = i;
            }
        } else {
            int n = i - N_EDGES;
            int gi = gate_gi(gate[n]);
            int l = lvl[n];
            if (gi >= 0 && l >= 1 && l <= 7) {
                int pos = atomicAdd(&g_ncur[(l - 1) * 3 + gi], 1);
                g_nlist[pos] = n;
            }
        }
    }
}

// ---------------- fused per-level message kernel --------------------------
// One launch per level, covering all 3 gate-type buckets. Block = 128 threads,
// tile = 32 edges. Thread owns 2 output cols (c0, c0+64) x 16 edges.
// x = [hs[src], hf[src]] -> 3-layer MLP -> atomicAdd scatter to g_msg[dst].
__global__ void __launch_bounds__(128) k_msg_lvl(
        const int* __restrict__ ei, const float* __restrict__ outbuf,
        const float* __restrict__ w1a, const float* __restrict__ b1a,
        const float* __restrict__ w2a, const float* __restrict__ b2a,
        const float* __restrict__ w3a, const float* __restrict__ b3a,
        int lvl) {
    __shared__ float4 xs4[MSG_TE][H2 / 4];   // 32 KB; also reused for h2
    __shared__ float4 h14[MSG_TE][H / 4];    // 16 KB
    __shared__ int ssrc[MSG_TE];
    __shared__ int sdst[MSG_TE];

    const int b0 = (lvl - 1) * 3;
    const int t0 = g_etile[b0];
    const int t3 = g_etile[b0 + 3];
    const int tid = threadIdx.x;
    const int lane = tid & 31, wrp = tid >> 5;
    const int c0 = tid & 63;                 // cols c0 and c0+64
    const int eh = tid >> 6;                 // edge half: 0 or 1
    const float* hf = outbuf + (size_t)N_NODES * H;

    for (int g = t0 + blockIdx.x; g < t3; g += gridDim.x) {
        int b = b0;
        while (b < b0 + 2 && g >= g_etile[b + 1]) b++;
        const int gi = b - b0;
        const int estart = g_eoff[b] + (g - g_etile[b]) * MSG_TE;
        const int ne = min(MSG_TE, g_eoff[b + 1] - estart);
        const float* __restrict__ w1 = w1a + (size_t)gi * H2 * H;
        const float* __restrict__ w2 = w2a + (size_t)gi * H * H;
        const float* __restrict__ w3 = w3a + (size_t)gi * H * H;

        // ---- stage edge endpoints ----
        if (tid < MSG_TE) {
            if (tid < ne) {
                int eid = g_elist[estart + tid];
                ssrc[tid] = ei[eid];
                sdst[tid] = ei[N_EDGES + eid];
            } else {
                ssrc[tid] = -1;
            }
        }
        __syncthreads();

        // ---- gather x = [hs[src], hf[src]] (float4, coalesced per warp) ----
        for (int p = wrp; p < 2 * MSG_TE; p += 4) {
            int e = p >> 1, half = p & 1;
            int src = ssrc[e];
            float4 v = make_float4(0.f, 0.f, 0.f, 0.f);
            if (src >= 0) {
                const float4* row = (const float4*)((half ? hf : outbuf) + (size_t)src * H);
                v = row[lane];
            }
            xs4[e][half * 32 + lane] = v;
        }
        __syncthreads();

        // ---- layer 1: [32,256] x [256,128] ----
        float acc0[16], acc1[16];
#pragma unroll
        for (int e = 0; e < 16; e++) { acc0[e] = 0.f; acc1[e] = 0.f; }
        for (int k4 = 0; k4 < H2 / 4; k4++) {
            const float* wr = w1 + (k4 * 4) * H;
            float wa0 = wr[c0],         wa1 = wr[H + c0],
                  wa2 = wr[2 * H + c0], wa3 = wr[3 * H + c0];
            float wb0 = wr[c0 + 64],         wb1 = wr[H + c0 + 64],
                  wb2 = wr[2 * H + c0 + 64], wb3 = wr[3 * H + c0 + 64];
#pragma unroll
            for (int e = 0; e < 16; e++) {
                float4 x = xs4[eh * 16 + e][k4];
                acc0[e] = fmaf(x.x, wa0, acc0[e]); acc0[e] = fmaf(x.y, wa1, acc0[e]);
                acc0[e] = fmaf(x.z, wa2, acc0[e]); acc0[e] = fmaf(x.w, wa3, acc0[e]);
                acc1[e] = fmaf(x.x, wb0, acc1[e]); acc1[e] = fmaf(x.y, wb1, acc1[e]);
                acc1[e] = fmaf(x.z, wb2, acc1[e]); acc1[e] = fmaf(x.w, wb3, acc1[e]);
            }
        }
        {
            float bb0 = b1a[gi * H + c0], bb1 = b1a[gi * H + c0 + 64];
            float* h1f = (float*)h14;
#pragma unroll
            for (int e = 0; e < 16; e++) {
                int ge = eh * 16 + e;
                h1f[ge * H + c0]      = fmaxf(acc0[e] + bb0, 0.f);
                h1f[ge * H + c0 + 64] = fmaxf(acc1[e] + bb1, 0.f);
            }
        }
        __syncthreads();

        // ---- layer 2: [32,128] x [128,128] -> h2 (reuse xs4 storage) ----
#pragma unroll
        for (int e = 0; e < 16; e++) { acc0[e] = 0.f; acc1[e] = 0.f; }
        for (int k4 = 0; k4 < H / 4; k4++) {
            const float* wr = w2 + (k4 * 4) * H;
            float wa0 = wr[c0],         wa1 = wr[H + c0],
                  wa2 = wr[2 * H + c0], wa3 = wr[3 * H + c0];
            float wb0 = wr[c0 + 64],         wb1 = wr[H + c0 + 64],
                  wb2 = wr[2 * H + c0 + 64], wb3 = wr[3 * H + c0 + 64];
#pragma unroll
            for (int e = 0; e < 16; e++) {
                float4 x = h14[eh * 16 + e][k4];
                acc0[e] = fmaf(x.x, wa0, acc0[e]); acc0[e] = fmaf(x.y, wa1, acc0[e]);
                acc0[e] = fmaf(x.z, wa2, acc0[e]); acc0[e] = fmaf(x.w, wa3, acc0[e]);
                acc1[e] = fmaf(x.x, wb0, acc1[e]); acc1[e] = fmaf(x.y, wb1, acc1[e]);
                acc1[e] = fmaf(x.z, wb2, acc1[e]); acc1[e] = fmaf(x.w, wb3, acc1[e]);
            }
        }
        __syncthreads();   // xs4 reads from stage are long done; safe to overwrite
        {
            float bb0 = b2a[gi * H + c0], bb1 = b2a[gi * H + c0 + 64];
            float* h2f = (float*)xs4;    // [e][128] packed rows
#pragma unroll
            for (int e = 0; e < 16; e++) {
                int ge = eh * 16 + e;
                h2f[ge * H + c0]      = fmaxf(acc0[e] + bb0, 0.f);
                h2f[ge * H + c0 + 64] = fmaxf(acc1[e] + bb1, 0.f);
            }
        }
        __syncthreads();

        // ---- layer 3: [32,128] x [128,128] -> scatter-add ----
#pragma unroll
        for (int e = 0; e < 16; e++) { acc0[e] = 0.f; acc1[e] = 0.f; }
        const float4* h24 = (const float4*)xs4;
        for (int k4 = 0; k4 < H / 4; k4++) {
            const float* wr = w3 + (k4 * 4) * H;
            float wa0 = wr[c0],         wa1 = wr[H + c0],
                  wa2 = wr[2 * H + c0], wa3 = wr[3 * H + c0];
            float wb0 = wr[c0 + 64],         wb1 = wr[H + c0 + 64],
                  wb2 = wr[2 * H + c0 + 64], wb3 = wr[3 * H + c0 + 64];
#pragma unroll
            for (int e = 0; e < 16; e++) {
                float4 x = h24[(eh * 16 + e) * (H / 4) + k4];
                acc0[e] = fmaf(x.x, wa0, acc0[e]); acc0[e] = fmaf(x.y, wa1, acc0[e]);
                acc0[e] = fmaf(x.z, wa2, acc0[e]); acc0[e] = fmaf(x.w, wa3, acc0[e]);
                acc1[e] = fmaf(x.x, wb0, acc1[e]); acc1[e] = fmaf(x.y, wb1, acc1[e]);
                acc1[e] = fmaf(x.z, wb2, acc1[e]); acc1[e] = fmaf(x.w, wb3, acc1[e]);
            }
        }
        {
            float bb0 = b3a[gi * H + c0], bb1 = b3a[gi * H + c0 + 64];
            for (int e = 0; e < 16; e++) {
                int ge = eh * 16 + e;
                if (ge < ne) {
                    int d = sdst[ge];
                    atomicAdd(&g_msg[(size_t)d * H + c0],      acc0[e] + bb0);
                    atomicAdd(&g_msg[(size_t)d * H + c0 + 64], acc1[e] + bb1);
                }
            }
        }
        __syncthreads();
    }
}

// ---------------- fused per-level GRU kernel ------------------------------
// h_old is provably zero (each node is updated exactly once), so the whh GEMM
// collapses to the bhh bias. gin = msg @ wih^T + bih; hf = (1-z)*tanh(...).
// Block = 128 threads (thread = feature j), tile = 16 nodes.
__global__ void __launch_bounds__(128) k_gru_lvl(
        const float* __restrict__ bih_a, const float* __restrict__ bhh_a,
        float* __restrict__ outbuf, int lvl) {
    __shared__ float4 ms4[GRU_TN][H / 4];    // 8 KB
    __shared__ int snode[GRU_TN];

    const int b0 = (lvl - 1) * 3;
    const int t0 = g_ntile[b0];
    const int t3 = g_ntile[b0 + 3];
    const int tid = threadIdx.x;
    const int lane = tid & 31, wrp = tid >> 5;
    const int j = tid;
    float* hf = outbuf + (size_t)N_NODES * H;

    for (int g = t0 + blockIdx.x; g < t3; g += gridDim.x) {
        int b = b0;
        while (b < b0 + 2 && g >= g_ntile[b + 1]) b++;
        const int gi = b - b0;
        const int nstart = g_noff[b] + (g - g_ntile[b]) * GRU_TN;
        const int nn = min(GRU_TN, g_noff[b + 1] - nstart);
        const float* __restrict__ wihT = g_wihT + (size_t)gi * H * H3;

        if (tid < GRU_TN)
            snode[tid] = (tid < nn) ? g_nlist[nstart + tid] : -1;
        __syncthreads();

        for (int p = wrp; p < GRU_TN; p += 4) {
            int node = snode[p];
            float4 v = make_float4(0.f, 0.f, 0.f, 0.f);
            if (node >= 0) v = ((const float4*)(g_msg + (size_t)node * H))[lane];
            ms4[p][lane] = v;
        }
        __syncthreads();

        float ar[GRU_TN], az[GRU_TN], an[GRU_TN];
#pragma unroll
        for (int e = 0; e < GRU_TN; e++) { ar[e] = 0.f; az[e] = 0.f; an[e] = 0.f; }

        for (int k4 = 0; k4 < H / 4; k4++) {
            const float* wr = wihT + (size_t)(k4 * 4) * H3;
            float r0 = wr[j],            r1 = wr[H3 + j],
                  r2 = wr[2 * H3 + j],   r3 = wr[3 * H3 + j];
            float z0 = wr[H + j],           z1 = wr[H3 + H + j],
                  z2 = wr[2 * H3 + H + j],  z3 = wr[3 * H3 + H + j];
            float n0 = wr[2 * H + j],          n1 = wr[H3 + 2 * H + j],
                  n2 = wr[2 * H3 + 2 * H + j], n3 = wr[3 * H3 + 2 * H + j];
#pragma unroll
            for (int e = 0; e < GRU_TN; e++) {
                float4 m = ms4[e][k4];
                ar[e] = fmaf(m.x, r0, ar[e]); ar[e] = fmaf(m.y, r1, ar[e]);
                ar[e] = fmaf(m.z, r2, ar[e]); ar[e] = fmaf(m.w, r3, ar[e]);
                az[e] = fmaf(m.x, z0, az[e]); az[e] = fmaf(m.y, z1, az[e]);
                az[e] = fmaf(m.z, z2, az[e]); az[e] = fmaf(m.w, z3, az[e]);
                an[e] = fmaf(m.x, n0, an[e]); an[e] = fmaf(m.y, n1, an[e]);
                an[e] = fmaf(m.z, n2, an[e]); an[e] = fmaf(m.w, n3, an[e]);
            }
        }

        const float bir = bih_a[gi * H3 + j]            + bhh_a[gi * H3 + j];
        const float biz = bih_a[gi * H3 + H + j]        + bhh_a[gi * H3 + H + j];
        const float bin_ = bih_a[gi * H3 + 2 * H + j];
        const float bhn  = bhh_a[gi * H3 + 2 * H + j];
        for (int e = 0; e < GRU_TN; e++) {
            int node = snode[e];
            if (node >= 0) {
                float r = 1.0f / (1.0f + expf(-(ar[e] + bir)));
                float z = 1.0f / (1.0f + expf(-(az[e] + biz)));
                float nst = tanhf(an[e] + bin_ + r * bhn);
                hf[(size_t)node * H + j] = (1.0f - z) * nst;
            }
        }
        __syncthreads();
    }
}

// ---------------- launch ---------------------------------------------------

extern "C" void kernel_launch(void* const* d_in, const int* in_sizes, int n_in,
                              void* d_out, int out_size) {
    const int* gate    = (const int*)d_in[0];
    const int* flevel  = (const int*)d_in[1];
    const int* ei      = (const int*)d_in[2];
    const float* Ws    = (const float*)d_in[3];
    const float* Wt    = (const float*)d_in[4];
    const float* hs_W  = (const float*)d_in[5];
    const float* hs_b  = (const float*)d_in[6];
    const float* w1    = (const float*)d_in[7];
    const float* b1    = (const float*)d_in[8];
    const float* w2    = (const float*)d_in[9];
    const float* b2    = (const float*)d_in[10];
    const float* w3    = (const float*)d_in[11];
    const float* b3    = (const float*)d_in[12];
    const float* wih   = (const float*)d_in[13];
    const float* bih   = (const float*)d_in[15];
    const float* bhh   = (const float*)d_in[16];
    float* out = (float*)d_out;

    k_init_counts<<<1, 64>>>();
    k_hs_type<<<6, H>>>(Ws, Wt, hs_W, hs_b);
    k_transpose<<<256, 256>>>(wih);
    k_hs_fill<<<2048, 256>>>((float4*)out, gate);
    k_count<<<1024, 256>>>(ei, gate, flevel);
    k_scan<<<1, 32>>>();
    k_fill_lists<<<1024, 256>>>(ei, gate, flevel);

    for (int lvl = 1; lvl <= 7; lvl++) {
        k_msg_lvl<<<1184, 128>>>(ei, out, w1, b1, w2, b2, w3, b3, lvl);
        k_gru_lvl<<<1184, 128>>>(bih, bhh, out, lvl);
    }
}

// round 8
// speedup vs baseline: 3.5943x; 1.3252x over previous
#include <cuda_runtime.h>
#include <math.h>

#define N_NODES 100000
#define N_EDGES 200000
#define H 128
#define H2 256
#define H3 384
#define NLVL 7
#define NBUCK_E 42        // 7 levels x 3 gate types x {nonzero-hf, zero-hf}
#define NBUCK_N 21        // 7 levels x 3 gate types
#define MSG_TE 32         // edges per msg tile
#define GRU_TN 16         // nodes per gru tile

// ---------------- device scratch (static: no allocations allowed) ----------
__device__ float g_msg[(size_t)N_NODES * H];   // scatter-add target
__device__ float g_hs_type[6 * H];             // per-gate-type hs row
__device__ float g_hsl1[3 * 6 * H];            // layer1 hs-half table [gi][gtype][j]
__device__ float g_wihT[3 * H * H3];           // transposed GRU input weights [gi][k][row]
__device__ int g_ecount[NBUCK_E];
__device__ int g_eoff[NBUCK_E + 1];
__device__ int g_ecur[NBUCK_E];
__device__ int g_etile[NBUCK_E + 1];
__device__ int g_ncount[NBUCK_N];
__device__ int g_noff[NBUCK_N + 1];
__device__ int g_ncur[NBUCK_N];
__device__ int g_ntile[NBUCK_N + 1];
__device__ int g_elist[N_EDGES];
__device__ int g_nlist[N_NODES];

__device__ __forceinline__ int gate_gi(int g) {
    // GATE_CODES = (3, 2, 5) -> gi 0, 1, 2
    return (g == 3) ? 0 : (g == 2) ? 1 : (g == 5) ? 2 : -1;
}

// edge bucket: (l-1)*6 + gi*2 + z   (z=1: hf[src] statically zero)
__device__ __forceinline__ int edge_bucket(int src, int dst,
                                           const int* gate, const int* lvl) {
    int gi = gate_gi(gate[dst]);
    int l = lvl[dst];
    if (gi < 0 || l < 1 || l > NLVL) return -1;
    int gs = gate_gi(gate[src]);
    int ls = lvl[src];
    int z = !(gs >= 0 && ls >= 1 && ls < l);
    return (l - 1) * 6 + gi * 2 + z;
}

// ---------------- setup kernels -------------------------------------------

__global__ void k_init_counts() {
    int t = threadIdx.x;
    if (t < NBUCK_E) g_ecount[t] = 0;
    if (t < NBUCK_N) g_ncount[t] = 0;
}

// hs_type[g][j] = concat(Ws[g], Wt[g]) @ hs_W + hs_b
__global__ void k_hs_type(const float* __restrict__ Ws, const float* __restrict__ Wt,
                          const float* __restrict__ hsW, const float* __restrict__ hsb) {
    int g = blockIdx.x;      // 0..5
    int j = threadIdx.x;     // 0..127
    float acc = hsb[j];
#pragma unroll 4
    for (int k = 0; k < H; k++)
        acc = fmaf(Ws[g * H + k], hsW[k * H + j], acc);
#pragma unroll 4
    for (int k = 0; k < H; k++)
        acc = fmaf(Wt[g * H + k], hsW[(H + k) * H + j], acc);
    g_hs_type[g * H + j] = acc;
}

// layer1 hs-half table: hsl1[gi][g][j] = sum_k hs_type[g][k] * w1[gi][k][j]
__global__ void k_hsl1(const float* __restrict__ w1) {
    int gi = blockIdx.x;     // 0..2
    int g = blockIdx.y;      // 0..5
    int j = threadIdx.x;     // 0..127
    const float* w = w1 + (size_t)gi * H2 * H;
    float acc = 0.f;
#pragma unroll 4
    for (int k = 0; k < H; k++)
        acc = fmaf(g_hs_type[g * H + k], w[k * H + j], acc);
    g_hsl1[(gi * 6 + g) * H + j] = acc;
}

// transpose GRU input weights: wihT[gi][k][r] = wih[gi][r][k]
__global__ void k_transpose(const float* __restrict__ wih) {
    const int total = 3 * H3 * H;
    for (int i = blockIdx.x * blockDim.x + threadIdx.x; i < total; i += gridDim.x * blockDim.x) {
        int gi = i / (H3 * H);
        int rem = i - gi * (H3 * H);
        int r = rem / H;
        int k = rem - r * H;
        g_wihT[gi * H * H3 + k * H3 + r] = wih[i];
    }
}

// write hs to out[0:NH), zero hf region out[NH:2NH), zero msg buffer (float4)
__global__ void k_hs_fill(float4* __restrict__ out4, const int* __restrict__ gate) {
    const int total4 = N_NODES * (H / 4);
    const float4* hs4 = (const float4*)g_hs_type;
    float4* msg4 = (float4*)g_msg;
    const float4 z4 = make_float4(0.f, 0.f, 0.f, 0.f);
    for (int i = blockIdx.x * blockDim.x + threadIdx.x; i < total4; i += gridDim.x * blockDim.x) {
        int node = i >> 5;               // H/4 = 32 float4 per row
        int c = i & 31;
        out4[i] = hs4[gate[node] * 32 + c];
        out4[total4 + i] = z4;
        msg4[i] = z4;
    }
}

// count edges/nodes per bucket
__global__ void k_count(const int* __restrict__ ei, const int* __restrict__ gate,
                        const int* __restrict__ lvl) {
    const int total = N_EDGES + N_NODES;
    for (int i = blockIdx.x * blockDim.x + threadIdx.x; i < total; i += gridDim.x * blockDim.x) {
        if (i < N_EDGES) {
            int b = edge_bucket(ei[i], ei[N_EDGES + i], gate, lvl);
            if (b >= 0) atomicAdd(&g_ecount[b], 1);
        } else {
            int n = i - N_EDGES;
            int gi = gate_gi(gate[n]);
            int l = lvl[n];
            if (gi >= 0 && l >= 1 && l <= NLVL) atomicAdd(&g_ncount[(l - 1) * 3 + gi], 1);
        }
    }
}

__global__ void k_scan() {
    if (threadIdx.x == 0) {
        int s = 0, st = 0;
        for (int b = 0; b < NBUCK_E; b++) {
            g_eoff[b] = s; g_ecur[b] = s; g_etile[b] = st;
            st += (g_ecount[b] + MSG_TE - 1) / MSG_TE;
            s += g_ecount[b];
        }
        g_eoff[NBUCK_E] = s; g_etile[NBUCK_E] = st;
        s = 0; st = 0;
        for (int b = 0; b < NBUCK_N; b++) {
            g_noff[b] = s; g_ncur[b] = s; g_ntile[b] = st;
            st += (g_ncount[b] + GRU_TN - 1) / GRU_TN;
            s += g_ncount[b];
        }
        g_noff[NBUCK_N] = s; g_ntile[NBUCK_N] = st;
    }
}

__global__ void k_fill_lists(const int* __restrict__ ei, const int* __restrict__ gate,
                             const int* __restrict__ lvl) {
    const int total = N_EDGES + N_NODES;
    for (int i = blockIdx.x * blockDim.x + threadIdx.x; i < total; i += gridDim.x * blockDim.x) {
        if (i < N_EDGES) {
            int b = edge_bucket(ei[i], ei[N_EDGES + i], gate, lvl);
            if (b >= 0) {
                int pos = atomicAdd(&g_ecur[b], 1);
                g_elist[pos] = i;
            }
        } else {
            int n = i - N_EDGES;
            int gi = gate_gi(gate[n]);
            int l = lvl[n];
            if (gi >= 0 && l >= 1 && l <= NLVL) {
                int pos = atomicAdd(&g_ncur[(l - 1) * 3 + gi], 1);
                g_nlist[pos] = n;
            }
        }
    }
}

// ---------------- fused per-level message kernel --------------------------
// One launch per level, covering 6 sub-buckets (3 gate types x {hf, no-hf}).
// Block = 128 threads, tile = 32 edges. Thread owns cols (c0, c0+64) x 16 edges.
// layer1 = hsl1-table[gate[src]] (+ hf[src] @ w1[128:256] if z==0) + b1.
__global__ void __launch_bounds__(128) k_msg_lvl(
        const int* __restrict__ ei, const float* __restrict__ outbuf,
        const float* __restrict__ w1a, const float* __restrict__ b1a,
        const float* __restrict__ w2a, const float* __restrict__ b2a,
        const float* __restrict__ w3a, const float* __restrict__ b3a,
        int lvl) {
    __shared__ float4 hfs4[MSG_TE][H / 4];   // 16 KB: hf[src] stage (z==0 only)
    __shared__ float4 h14[MSG_TE][H / 4];    // 16 KB
    __shared__ float4 h24[MSG_TE][H / 4];    // 16 KB
    __shared__ int sdst[MSG_TE];
    __shared__ int sgt[MSG_TE];              // gate[src]

    const int b0 = (lvl - 1) * 6;
    const int t0 = g_etile[b0];
    const int t6 = g_etile[b0 + 6];
    const int tid = threadIdx.x;
    const int lane = tid & 31, wrp = tid >> 5;
    const int c0 = tid & 63;                 // cols c0 and c0+64
    const int eh = tid >> 6;                 // edge half: 0 or 1
    const float* hf = outbuf + (size_t)N_NODES * H;

    for (int g = t0 + blockIdx.x; g < t6; g += gridDim.x) {
        int b = b0;
        while (b < b0 + 5 && g >= g_etile[b + 1]) b++;
        const int sub = b - b0;
        const int gi = sub >> 1;
        const int hfz = sub & 1;             // 1 -> hf[src] all zero, skip GEMM
        const int estart = g_eoff[b] + (g - g_etile[b]) * MSG_TE;
        const int ne = min(MSG_TE, g_eoff[b + 1] - estart);
        const float* __restrict__ w1 = w1a + (size_t)gi * H2 * H;
        const float* __restrict__ w2 = w2a + (size_t)gi * H * H;
        const float* __restrict__ w3 = w3a + (size_t)gi * H * H;
        const float* __restrict__ tbl = g_hsl1 + (size_t)gi * 6 * H;

        // ---- stage edge endpoints + src gate type (+ hf rows if needed) ----
        int my_src = -1;
        if (tid < MSG_TE) {
            if (tid < ne) {
                int eid = g_elist[estart + tid];
                my_src = ei[eid];
                sdst[tid] = ei[N_EDGES + eid];
                sgt[tid] = ((const int*)0 == 0) ? 0 : 0;  // placeholder overwritten below
            }
        }
        // gate[src] lookup (separate to keep loads batched)
        if (tid < MSG_TE) {
            const int* gate_arr = (const int*)nullptr;
            (void)gate_arr;
        }
        __syncthreads();
        // NOTE: sgt filled via second pass below using g_elist again (needs gate array);
        // gate pointer passed via ei? -- handled by caller packing; see k_msg_gt.

        // This block intentionally unreachable placeholder-free path (real code below)
        break;
    }
}

// real msg kernel (takes gate array explicitly)
__global__ void __launch_bounds__(128) k_msg_lvl2(
        const int* __restrict__ ei, const int* __restrict__ gate,
        const float* __restrict__ outbuf,
        const float* __restrict__ w1a, const float* __restrict__ b1a,
        const float* __restrict__ w2a, const float* __restrict__ b2a,
        const float* __restrict__ w3a, const float* __restrict__ b3a,
        int lvl) {
    __shared__ float4 hfs4[MSG_TE][H / 4];   // 16 KB: hf[src] stage (z==0 only)
    __shared__ float4 h14[MSG_TE][H / 4];    // 16 KB
    __shared__ float4 h24[MSG_TE][H / 4];    // 16 KB
    __shared__ int ssrc[MSG_TE];
    __shared__ int sdst[MSG_TE];
    __shared__ int sgt[MSG_TE];              // gate[src]

    const int b0 = (lvl - 1) * 6;
    const int t0 = g_etile[b0];
    const int t6 = g_etile[b0 + 6];
    const int tid = threadIdx.x;
    const int lane = tid & 31, wrp = tid >> 5;
    const int c0 = tid & 63;                 // cols c0 and c0+64
    const int eh = tid >> 6;                 // edge half: 0 or 1
    const float* hf = outbuf + (size_t)N_NODES * H;

    for (int g = t0 + blockIdx.x; g < t6; g += gridDim.x) {
        int b = b0;
        while (b < b0 + 5 && g >= g_etile[b + 1]) b++;
        const int sub = b - b0;
        const int gi = sub >> 1;
        const int hfz = sub & 1;             // 1 -> hf[src] statically zero
        const int estart = g_eoff[b] + (g - g_etile[b]) * MSG_TE;
        const int ne = min(MSG_TE, g_eoff[b + 1] - estart);
        const float* __restrict__ w1 = w1a + (size_t)gi * H2 * H;
        const float* __restrict__ w2 = w2a + (size_t)gi * H * H;
        const float* __restrict__ w3 = w3a + (size_t)gi * H * H;
        const float* __restrict__ tbl = g_hsl1 + (size_t)gi * 6 * H;

        // ---- stage edge endpoints + src gate type ----
        if (tid < MSG_TE) {
            if (tid < ne) {
                int eid = g_elist[estart + tid];
                int src = ei[eid];
                ssrc[tid] = src;
                sdst[tid] = ei[N_EDGES + eid];
                sgt[tid] = gate[src];
            } else {
                ssrc[tid] = -1;
                sgt[tid] = 0;
            }
        }
        __syncthreads();

        // ---- layer 1 ----
        float acc0[16], acc1[16];
        if (hfz) {
            // pure table lookup, no node-state gather at all
#pragma unroll
            for (int e = 0; e < 16; e++) {
                int gt = sgt[eh * 16 + e];
                acc0[e] = __ldg(&tbl[gt * H + c0]);
                acc1[e] = __ldg(&tbl[gt * H + c0 + 64]);
            }
        } else {
            // gather hf[src] (float4, coalesced per warp)
            for (int p = wrp; p < MSG_TE; p += 4) {
                int src = ssrc[p];
                float4 v = make_float4(0.f, 0.f, 0.f, 0.f);
                if (src >= 0) v = ((const float4*)(hf + (size_t)src * H))[lane];
                hfs4[p][lane] = v;
            }
#pragma unroll
            for (int e = 0; e < 16; e++) {
                int gt = sgt[eh * 16 + e];
                acc0[e] = __ldg(&tbl[gt * H + c0]);
                acc1[e] = __ldg(&tbl[gt * H + c0 + 64]);
            }
            __syncthreads();
            const float* w1b = w1 + (size_t)H * H;   // hf half: rows 128..255
            for (int k4 = 0; k4 < H / 4; k4++) {
                const float* wr = w1b + (k4 * 4) * H;
                float wa0 = wr[c0],         wa1 = wr[H + c0],
                      wa2 = wr[2 * H + c0], wa3 = wr[3 * H + c0];
                float wb0 = wr[c0 + 64],         wb1 = wr[H + c0 + 64],
                      wb2 = wr[2 * H + c0 + 64], wb3 = wr[3 * H + c0 + 64];
#pragma unroll
                for (int e = 0; e < 16; e++) {
                    float4 x = hfs4[eh * 16 + e][k4];
                    acc0[e] = fmaf(x.x, wa0, acc0[e]); acc0[e] = fmaf(x.y, wa1, acc0[e]);
                    acc0[e] = fmaf(x.z, wa2, acc0[e]); acc0[e] = fmaf(x.w, wa3, acc0[e]);
                    acc1[e] = fmaf(x.x, wb0, acc1[e]); acc1[e] = fmaf(x.y, wb1, acc1[e]);
                    acc1[e] = fmaf(x.z, wb2, acc1[e]); acc1[e] = fmaf(x.w, wb3, acc1[e]);
                }
            }
        }
        {
            float bb0 = b1a[gi * H + c0], bb1 = b1a[gi * H + c0 + 64];
            float* h1f = (float*)h14;
#pragma unroll
            for (int e = 0; e < 16; e++) {
                int ge = eh * 16 + e;
                h1f[ge * H + c0]      = fmaxf(acc0[e] + bb0, 0.f);
                h1f[ge * H + c0 + 64] = fmaxf(acc1[e] + bb1, 0.f);
            }
        }
        __syncthreads();

        // ---- layer 2: [32,128] x [128,128] ----
#pragma unroll
        for (int e = 0; e < 16; e++) { acc0[e] = 0.f; acc1[e] = 0.f; }
        for (int k4 = 0; k4 < H / 4; k4++) {
            const float* wr = w2 + (k4 * 4) * H;
            float wa0 = wr[c0],         wa1 = wr[H + c0],
                  wa2 = wr[2 * H + c0], wa3 = wr[3 * H + c0];
            float wb0 = wr[c0 + 64],         wb1 = wr[H + c0 + 64],
                  wb2 = wr[2 * H + c0 + 64], wb3 = wr[3 * H + c0 + 64];
#pragma unroll
            for (int e = 0; e < 16; e++) {
                float4 x = h14[eh * 16 + e][k4];
                acc0[e] = fmaf(x.x, wa0, acc0[e]); acc0[e] = fmaf(x.y, wa1, acc0[e]);
                acc0[e] = fmaf(x.z, wa2, acc0[e]); acc0[e] = fmaf(x.w, wa3, acc0[e]);
                acc1[e] = fmaf(x.x, wb0, acc1[e]); acc1[e] = fmaf(x.y, wb1, acc1[e]);
                acc1[e] = fmaf(x.z, wb2, acc1[e]); acc1[e] = fmaf(x.w, wb3, acc1[e]);
            }
        }
        {
            float bb0 = b2a[gi * H + c0], bb1 = b2a[gi * H + c0 + 64];
            float* h2f = (float*)h24;
#pragma unroll
            for (int e = 0; e < 16; e++) {
                int ge = eh * 16 + e;
                h2f[ge * H + c0]      = fmaxf(acc0[e] + bb0, 0.f);
                h2f[ge * H + c0 + 64] = fmaxf(acc1[e] + bb1, 0.f);
            }
        }
        __syncthreads();

        // ---- layer 3: [32,128] x [128,128] -> scatter-add ----
#pragma unroll
        for (int e = 0; e < 16; e++) { acc0[e] = 0.f; acc1[e] = 0.f; }
        for (int k4 = 0; k4 < H / 4; k4++) {
            const float* wr = w3 + (k4 * 4) * H;
            float wa0 = wr[c0],         wa1 = wr[H + c0],
                  wa2 = wr[2 * H + c0], wa3 = wr[3 * H + c0];
            float wb0 = wr[c0 + 64],         wb1 = wr[H + c0 + 64],
                  wb2 = wr[2 * H + c0 + 64], wb3 = wr[3 * H + c0 + 64];
#pragma unroll
            for (int e = 0; e < 16; e++) {
                float4 x = h24[eh * 16 + e][k4];
                acc0[e] = fmaf(x.x, wa0, acc0[e]); acc0[e] = fmaf(x.y, wa1, acc0[e]);
                acc0[e] = fmaf(x.z, wa2, acc0[e]); acc0[e] = fmaf(x.w, wa3, acc0[e]);
                acc1[e] = fmaf(x.x, wb0, acc1[e]); acc1[e] = fmaf(x.y, wb1, acc1[e]);
                acc1[e] = fmaf(x.z, wb2, acc1[e]); acc1[e] = fmaf(x.w, wb3, acc1[e]);
            }
        }
        {
            float bb0 = b3a[gi * H + c0], bb1 = b3a[gi * H + c0 + 64];
            for (int e = 0; e < 16; e++) {
                int ge = eh * 16 + e;
                if (ge < ne) {
                    int d = sdst[ge];
                    atomicAdd(&g_msg[(size_t)d * H + c0],      acc0[e] + bb0);
                    atomicAdd(&g_msg[(size_t)d * H + c0 + 64], acc1[e] + bb1);
                }
            }
        }
        __syncthreads();
    }
}

// ---------------- fused per-level GRU kernel ------------------------------
// h_old is provably zero (each node updated exactly once): whh GEMM -> bhh bias.
__global__ void __launch_bounds__(128) k_gru_lvl(
        const float* __restrict__ bih_a, const float* __restrict__ bhh_a,
        float* __restrict__ outbuf, int lvl) {
    __shared__ float4 ms4[GRU_TN][H / 4];    // 8 KB
    __shared__ int snode[GRU_TN];

    const int b0 = (lvl - 1) * 3;
    const int t0 = g_ntile[b0];
    const int t3 = g_ntile[b0 + 3];
    const int tid = threadIdx.x;
    const int lane = tid & 31, wrp = tid >> 5;
    const int j = tid;
    float* hf = outbuf + (size_t)N_NODES * H;

    for (int g = t0 + blockIdx.x; g < t3; g += gridDim.x) {
        int b = b0;
        while (b < b0 + 2 && g >= g_ntile[b + 1]) b++;
        const int gi = b - b0;
        const int nstart = g_noff[b] + (g - g_ntile[b]) * GRU_TN;
        const int nn = min(GRU_TN, g_noff[b + 1] - nstart);
        const float* __restrict__ wihT = g_wihT + (size_t)gi * H * H3;

        if (tid < GRU_TN)
            snode[tid] = (tid < nn) ? g_nlist[nstart + tid] : -1;
        __syncthreads();

        for (int p = wrp; p < GRU_TN; p += 4) {
            int node = snode[p];
            float4 v = make_float4(0.f, 0.f, 0.f, 0.f);
            if (node >= 0) v = ((const float4*)(g_msg + (size_t)node * H))[lane];
            ms4[p][lane] = v;
        }
        __syncthreads();

        float ar[GRU_TN], az[GRU_TN], an[GRU_TN];
#pragma unroll
        for (int e = 0; e < GRU_TN; e++) { ar[e] = 0.f; az[e] = 0.f; an[e] = 0.f; }

        for (int k4 = 0; k4 < H / 4; k4++) {
            const float* wr = wihT + (size_t)(k4 * 4) * H3;
            float r0 = wr[j],            r1 = wr[H3 + j],
                  r2 = wr[2 * H3 + j],   r3 = wr[3 * H3 + j];
            float z0 = wr[H + j],           z1 = wr[H3 + H + j],
                  z2 = wr[2 * H3 + H + j],  z3 = wr[3 * H3 + H + j];
            float n0 = wr[2 * H + j],          n1 = wr[H3 + 2 * H + j],
                  n2 = wr[2 * H3 + 2 * H + j], n3 = wr[3 * H3 + 2 * H + j];
#pragma unroll
            for (int e = 0; e < GRU_TN; e++) {
                float4 m = ms4[e][k4];
                ar[e] = fmaf(m.x, r0, ar[e]); ar[e] = fmaf(m.y, r1, ar[e]);
                ar[e] = fmaf(m.z, r2, ar[e]); ar[e] = fmaf(m.w, r3, ar[e]);
                az[e] = fmaf(m.x, z0, az[e]); az[e] = fmaf(m.y, z1, az[e]);
                az[e] = fmaf(m.z, z2, az[e]); az[e] = fmaf(m.w, z3, az[e]);
                an[e] = fmaf(m.x, n0, an[e]); an[e] = fmaf(m.y, n1, an[e]);
                an[e] = fmaf(m.z, n2, an[e]); an[e] = fmaf(m.w, n3, an[e]);
            }
        }

        const float bir = bih_a[gi * H3 + j]            + bhh_a[gi * H3 + j];
        const float biz = bih_a[gi * H3 + H + j]        + bhh_a[gi * H3 + H + j];
        const float bin_ = bih_a[gi * H3 + 2 * H + j];
        const float bhn  = bhh_a[gi * H3 + 2 * H + j];
        for (int e = 0; e < GRU_TN; e++) {
            int node = snode[e];
            if (node >= 0) {
                float r = 1.0f / (1.0f + expf(-(ar[e] + bir)));
                float z = 1.0f / (1.0f + expf(-(az[e] + biz)));
                float nst = tanhf(an[e] + bin_ + r * bhn);
                hf[(size_t)node * H + j] = (1.0f - z) * nst;
            }
        }
        __syncthreads();
    }
}

// ---------------- launch ---------------------------------------------------

extern "C" void kernel_launch(void* const* d_in, const int* in_sizes, int n_in,
                              void* d_out, int out_size) {
    const int* gate    = (const int*)d_in[0];
    const int* flevel  = (const int*)d_in[1];
    const int* ei      = (const int*)d_in[2];
    const float* Ws    = (const float*)d_in[3];
    const float* Wt    = (const float*)d_in[4];
    const float* hs_W  = (const float*)d_in[5];
    const float* hs_b  = (const float*)d_in[6];
    const float* w1    = (const float*)d_in[7];
    const float* b1    = (const float*)d_in[8];
    const float* w2    = (const float*)d_in[9];
    const float* b2    = (const float*)d_in[10];
    const float* w3    = (const float*)d_in[11];
    const float* b3    = (const float*)d_in[12];
    const float* wih   = (const float*)d_in[13];
    const float* bih   = (const float*)d_in[15];
    const float* bhh   = (const float*)d_in[16];
    float* out = (float*)d_out;

    k_init_counts<<<1, 64>>>();
    k_hs_type<<<6, H>>>(Ws, Wt, hs_W, hs_b);
    k_hsl1<<<dim3(3, 6), H>>>(w1);
    k_transpose<<<256, 256>>>(wih);
    k_hs_fill<<<2048, 256>>>((float4*)out, gate);
    k_count<<<1024, 256>>>(ei, gate, flevel);
    k_scan<<<1, 32>>>();
    k_fill_lists<<<1024, 256>>>(ei, gate, flevel);

    for (int lvl = 1; lvl <= 7; lvl++) {
        k_msg_lvl2<<<1184, 128>>>(ei, gate, out, w1, b1, w2, b2, w3, b3, lvl);
        k_gru_lvl<<<1184, 128>>>(bih, bhh, out, lvl);
    }
}